// round 1
// baseline (speedup 1.0000x reference)
#include <cuda_runtime.h>
#include <cuda_bf16.h>

// Problem constants (fixed by the reference's setup_inputs)
#define BQ 4096
#define NQ 128
#define FQ 64
#define HIST 1024      // ids are in [0, 1000); -1 padding handled via unsigned compare
#define TROWS 129      // counts range 0..128 inclusive
#define TSTRIDE 68     // padded row stride (floats): 16B-aligned, avoids 64-stride bank conflicts

// Scratch: MLP lookup table. T[c][g] = b2[g] + sum_f relu(c*w1[f]+b1[f]) * w2[g*F+f]
__device__ float g_table[TROWS * FQ];

// ---------------------------------------------------------------------------
// Kernel 1: build the 129x64 MLP table. Trivial cost (~0.5M FMA).
// ---------------------------------------------------------------------------
__global__ void build_table_kernel(const float* __restrict__ w1,
                                   const float* __restrict__ b1,
                                   const float* __restrict__ w2,
                                   const float* __restrict__ b2) {
    const int c = blockIdx.x;    // count value 0..128
    const int g = threadIdx.x;   // output feature 0..63
    __shared__ float h[FQ];
    // w1 has shape (F,1) -> w1[f]
    h[g] = fmaxf((float)c * w1[g] + b1[g], 0.0f);
    __syncthreads();
    float acc = b2[g];
#pragma unroll
    for (int f = 0; f < FQ; f++) {
        acc += h[f] * w2[g * FQ + f];   // einsum 'bncf,gf->bncg' => w2[g, f]
    }
    g_table[c * FQ + g] = acc;
}

// ---------------------------------------------------------------------------
// Kernel 2: per-batch packed histogram + table gather + streamed output.
// 2 batches per 256-thread block. Shared = 35.1KB table + 8KB hists = 43.3KB.
// ---------------------------------------------------------------------------
__global__ __launch_bounds__(256)
void cooccur_kernel(const int* __restrict__ src,
                    const int* __restrict__ dst,
                    float* __restrict__ out) {
    __shared__ float sT[TROWS * TSTRIDE];
    __shared__ unsigned int hist[2][HIST];   // low 16 bits: src count, high 16: dst count

    const int tid = threadIdx.x;

    // Stage the table into shared (padded rows). 8256 floats / 256 threads.
    for (int idx = tid; idx < TROWS * FQ; idx += 256) {
        sT[(idx >> 6) * TSTRIDE + (idx & 63)] = g_table[idx];
    }
    // Zero both histograms.
    for (int idx = tid; idx < 2 * HIST; idx += 256) {
        (&hist[0][0])[idx] = 0u;
    }
    __syncthreads();

    const int lb = tid >> 7;          // local batch 0/1
    const int i  = tid & 127;         // element within batch
    const long long b = (long long)blockIdx.x * 2 + lb;

    const int s = src[b * NQ + i];
    const int d = dst[b * NQ + i];

    // Build packed histograms. (unsigned)(-1) >= HIST skips padded ids safely.
    if ((unsigned)s < HIST) atomicAdd(&hist[lb][s], 1u);
    if ((unsigned)d < HIST) atomicAdd(&hist[lb][d], 65536u);
    __syncthreads();

    // Co-occurrence counts. Padded id (-1) -> all-zero freq, matching the
    // reference's where(pad, 0, freq); MLP(0) is still applied via T[0].
    const unsigned hs = ((unsigned)s < HIST) ? hist[lb][s] : 0u;
    const unsigned hd = ((unsigned)d < HIST) ? hist[lb][d] : 0u;
    const int c_ss = (int)(hs & 0xFFFFu);   // #{j: src_i == src_j}
    const int c_sd = (int)(hs >> 16);       // #{j: src_i == dst_j}
    const int c_ds = (int)(hd & 0xFFFFu);   // #{j: dst_i == src_j}
    const int c_dd = (int)(hd >> 16);       // #{j: dst_i == dst_j}

    const float4* rs0 = (const float4*)&sT[c_ss * TSTRIDE];
    const float4* rs1 = (const float4*)&sT[c_sd * TSTRIDE];
    const float4* rd0 = (const float4*)&sT[c_dd * TSTRIDE];
    const float4* rd1 = (const float4*)&sT[c_ds * TSTRIDE];

    const size_t base = ((size_t)b * NQ + i) * FQ;
    float4* outs = (float4*)(out + base);                              // src_feat
    float4* outd = (float4*)(out + (size_t)BQ * NQ * FQ + base);       // dst_feat

#pragma unroll
    for (int k = 0; k < FQ / 4; k++) {
        float4 a = rs0[k], bb = rs1[k];
        a.x += bb.x; a.y += bb.y; a.z += bb.z; a.w += bb.w;
        __stcs(&outs[k], a);   // streaming store: output is never re-read
        float4 e = rd0[k], f4 = rd1[k];
        e.x += f4.x; e.y += f4.y; e.z += f4.z; e.w += f4.w;
        __stcs(&outd[k], e);
    }
}

// ---------------------------------------------------------------------------
// Launch. Inputs (metadata order): src_ids[B*N] i32, dst_ids[B*N] i32,
// w1[F] f32, b1[F] f32, w2[F*F] f32, b2[F] f32. Output: f32, 2*B*N*F
// (src_feat flattened, then dst_feat flattened).
// ---------------------------------------------------------------------------
extern "C" void kernel_launch(void* const* d_in, const int* in_sizes, int n_in,
                              void* d_out, int out_size) {
    const int*   src = (const int*)d_in[0];
    const int*   dst = (const int*)d_in[1];
    const float* w1  = (const float*)d_in[2];
    const float* b1  = (const float*)d_in[3];
    const float* w2  = (const float*)d_in[4];
    const float* b2  = (const float*)d_in[5];
    float* out = (float*)d_out;

    build_table_kernel<<<TROWS, FQ>>>(w1, b1, w2, b2);
    cooccur_kernel<<<BQ / 2, 256>>>(src, dst, out);
}

// round 2
// speedup vs baseline: 3.0819x; 3.0819x over previous
#include <cuda_runtime.h>
#include <cuda_bf16.h>

// Problem constants (fixed by the reference's setup_inputs)
#define BQ 4096
#define NQ 128
#define FQ 64
#define HIST 1024      // ids are in [0, 1000); -1 padding handled via unsigned compare
#define TROWS 129      // counts range 0..128 inclusive
#define TSTRIDE 68     // padded row stride (floats), 16B-aligned
#define BPB 4          // batches per block

// Scratch: MLP lookup table. T[c][g] = b2[g] + sum_f relu(c*w1[f]+b1[f]) * w2[g*F+f]
__device__ float g_table[TROWS * FQ];

// ---------------------------------------------------------------------------
// Kernel 1: build the 129x64 MLP table. Trivial cost (~0.5M FMA).
// ---------------------------------------------------------------------------
__global__ void build_table_kernel(const float* __restrict__ w1,
                                   const float* __restrict__ b1,
                                   const float* __restrict__ w2,
                                   const float* __restrict__ b2) {
    const int c = blockIdx.x;    // count value 0..128
    const int g = threadIdx.x;   // output feature 0..63
    __shared__ float h[FQ];
    h[g] = fmaxf((float)c * w1[g] + b1[g], 0.0f);   // w1 shape (F,1) -> w1[f]
    __syncthreads();
    float acc = b2[g];
#pragma unroll
    for (int f = 0; f < FQ; f++) {
        acc += h[f] * w2[g * FQ + f];   // einsum 'bncf,gf->bncg' => w2[g, f]
    }
    g_table[c * FQ + g] = acc;
}

// ---------------------------------------------------------------------------
// Kernel 2: 4 batches/block. Packed byte-histograms (2 batches x src/dst per
// u32 word), counts cached as uchar4, then fully-coalesced float4 writes.
// Shared: table 35088 + hist 8192 + cnts 2048 = 45328 B (< 48 KB static).
// ---------------------------------------------------------------------------
__global__ __launch_bounds__(256)
void cooccur_kernel(const int* __restrict__ src,
                    const int* __restrict__ dst,
                    float* __restrict__ out) {
    __shared__ float sT[TROWS * TSTRIDE];
    __shared__ unsigned int hist[2][HIST];  // word packs: b0.src[0:8) b0.dst[8:16) b1.src[16:24) b1.dst[24:32)
    __shared__ uchar4 cnts[BPB][NQ];        // (c_ss, c_sd, c_dd, c_ds) per element

    const int tid = threadIdx.x;

    // Stage table into shared (padded rows), zero histograms.
    for (int idx = tid; idx < TROWS * FQ; idx += 256) {
        sT[(idx >> 6) * TSTRIDE + (idx & 63)] = g_table[idx];
    }
    for (int idx = tid; idx < 2 * HIST; idx += 256) {
        (&hist[0][0])[idx] = 0u;
    }
    __syncthreads();

    // --- Histogram phase: 4 batches x 128 ids = 512 work items, 2 per thread.
    int s_ids[2], d_ids[2];
#pragma unroll
    for (int it = 0; it < 2; it++) {
        const int idx = it * 256 + tid;
        const int lb = idx >> 7;              // local batch 0..3
        const int i  = idx & 127;
        const long long b = (long long)blockIdx.x * BPB + lb;
        const int s = src[b * NQ + i];
        const int d = dst[b * NQ + i];
        s_ids[it] = s; d_ids[it] = d;
        const int p   = lb >> 1;              // which hist array
        const int sh  = (lb & 1) * 16;        // sub-batch shift
        if ((unsigned)s < HIST) atomicAdd(&hist[p][s], 1u << sh);
        if ((unsigned)d < HIST) atomicAdd(&hist[p][d], 1u << (sh + 8));
    }
    __syncthreads();

    // --- Count extraction: padded id (-1) -> zero counts (matches reference's
    // where(pad, 0, freq); MLP(0) still applied via table row 0).
#pragma unroll
    for (int it = 0; it < 2; it++) {
        const int idx = it * 256 + tid;
        const int lb = idx >> 7;
        const int i  = idx & 127;
        const int p  = lb >> 1;
        const int sh = (lb & 1) * 16;
        const int s = s_ids[it], d = d_ids[it];
        const unsigned hs = ((unsigned)s < HIST) ? hist[p][s] : 0u;
        const unsigned hd = ((unsigned)d < HIST) ? hist[p][d] : 0u;
        uchar4 c;
        c.x = (unsigned char)((hs >> sh)       & 0xFFu);  // c_ss
        c.y = (unsigned char)((hs >> (sh + 8)) & 0xFFu);  // c_sd
        c.z = (unsigned char)((hd >> (sh + 8)) & 0xFFu);  // c_dd
        c.w = (unsigned char)((hd >> sh)       & 0xFFu);  // c_ds
        cnts[lb][i] = c;
    }
    __syncthreads();

    // --- Coalesced write phase. Per batch, per output half: 128x64 floats =
    // 2048 float4 = 8 iterations of 256 threads. Consecutive threads write
    // consecutive float4s; table rows broadcast from shared.
    const size_t half = (size_t)BQ * NQ * FQ;
#pragma unroll
    for (int lb = 0; lb < BPB; lb++) {
        const size_t b = (size_t)blockIdx.x * BPB + lb;
        float4* const osrc = (float4*)(out + b * (NQ * FQ));
        float4* const odst = (float4*)(out + half + b * (NQ * FQ));
#pragma unroll
        for (int k = 0; k < 8; k++) {
            const int lin = k * 256 + tid;
            const int i   = lin >> 4;
            const int g4  = (lin & 15) * 4;
            const uchar4 c = cnts[lb][i];
            // src_feat = T[c_ss] + T[c_sd]
            float4 a  = *(const float4*)&sT[(int)c.x * TSTRIDE + g4];
            float4 a2 = *(const float4*)&sT[(int)c.y * TSTRIDE + g4];
            a.x += a2.x; a.y += a2.y; a.z += a2.z; a.w += a2.w;
            __stcs(&osrc[lin], a);
            // dst_feat = T[c_dd] + T[c_ds]
            float4 e  = *(const float4*)&sT[(int)c.z * TSTRIDE + g4];
            float4 e2 = *(const float4*)&sT[(int)c.w * TSTRIDE + g4];
            e.x += e2.x; e.y += e2.y; e.z += e2.z; e.w += e2.w;
            __stcs(&odst[lin], e);
        }
    }
}

// ---------------------------------------------------------------------------
// Launch. Inputs (metadata order): src_ids[B*N] i32, dst_ids[B*N] i32,
// w1[F] f32, b1[F] f32, w2[F*F] f32, b2[F] f32. Output: f32, 2*B*N*F
// (src_feat flattened, then dst_feat flattened).
// ---------------------------------------------------------------------------
extern "C" void kernel_launch(void* const* d_in, const int* in_sizes, int n_in,
                              void* d_out, int out_size) {
    const int*   src = (const int*)d_in[0];
    const int*   dst = (const int*)d_in[1];
    const float* w1  = (const float*)d_in[2];
    const float* b1  = (const float*)d_in[3];
    const float* w2  = (const float*)d_in[4];
    const float* b2  = (const float*)d_in[5];
    float* out = (float*)d_out;

    build_table_kernel<<<TROWS, FQ>>>(w1, b1, w2, b2);
    cooccur_kernel<<<BQ / BPB, 256>>>(src, dst, out);
}